// round 4
// baseline (speedup 1.0000x reference)
#include <cuda_runtime.h>

#define NB 4
#define PRE 512
#define NC 2048
#define TANCH 261120
#define NBIN 8192
#define CANDCAP 2048
#define NBLK 132
#define NT 512

// ---------------- scratch (device globals; zero-initialized) --------------
__device__ int g_hist[16][NBIN];
__device__ int g_ccnt[16];
__device__ unsigned g_count;   // barrier arrive counter (self-resetting)
__device__ unsigned g_gen;     // barrier generation (monotonic)
__device__ unsigned long long g_cand[16][CANDCAP];
__device__ float g_box[NB][NC][5];
__device__ float g_score[NB][NC];
__device__ unsigned char g_valid[NB][NC];
__device__ unsigned long long g_key[NB][NC];
__device__ float g_sbox[NB][NC][5];
__device__ float g_sscore[NB][NC];
__device__ unsigned char g_svalid[NB][NC];
__device__ float g_geom[NB][NC][16];   // x0..y3, area, cx, cy, r, xmin,xmax,ymin,ymax
__device__ unsigned long long g_mask[NB][NC][32];  // lower-tri words never written: stay 0

__device__ const int c_aoff[4] = {0, 196608, 245760, 258048};

__device__ __forceinline__ unsigned fflip(float f) {
    unsigned u = __float_as_uint(f);
    return (u & 0x80000000u) ? ~u : (u | 0x80000000u);
}
__device__ __forceinline__ float funflip(unsigned u) {
    return __uint_as_float((u & 0x80000000u) ? (u ^ 0x80000000u) : ~u);
}

// block mapping: 33 blocks per image
// lvl0: 24 x 8192, lvl1: 6 x 8192, lvl2: 2 x 6144, lvl3: 1 x 3072
__device__ __forceinline__ void map_block(int bx, int& b, int& lvl, int& c0, int& n) {
    b = bx / 33;
    int t = bx % 33;
    if (t < 24)      { lvl = 0; c0 = t * 8192;        n = 8192; }
    else if (t < 30) { lvl = 1; c0 = (t - 24) * 8192; n = 8192; }
    else if (t < 32) { lvl = 2; c0 = (t - 30) * 6144; n = 6144; }
    else             { lvl = 3; c0 = 0;               n = 3072; }
}

__device__ __forceinline__ void hist_add(int* h, unsigned bin) {
    unsigned m = __match_any_sync(0xffffffffu, bin);
    int leader = __ffs(m) - 1;
    if ((threadIdx.x & 31) == leader) atomicAdd(&h[bin], __popc(m));
}

// sense-reversing grid barrier; all 132 blocks co-resident (grid < #SMs)
__device__ __forceinline__ void grid_bar() {
    __syncthreads();
    if (threadIdx.x == 0) {
        __threadfence();
        unsigned gen = atomicAdd(&g_gen, 0u);
        if (atomicAdd(&g_count, 1u) == NBLK - 1u) {
            atomicExch(&g_count, 0u);
            atomicAdd(&g_gen, 1u);
        } else {
            while (atomicAdd(&g_gen, 0u) == gen) { }
        }
        __threadfence();
    }
    __syncthreads();
}

// Sutherland-Hodgman quad-quad intersection (reference arithmetic)
__device__ float inter_area(float4 pA, float4 pB, float4 qA, float4 qB) {
    float px[8], py[8], ox[8], oy[8];
    px[0] = pA.x; py[0] = pA.y; px[1] = pA.z; py[1] = pA.w;
    px[2] = pB.x; py[2] = pB.y; px[3] = pB.z; py[3] = pB.w;
    float qx[4] = {qA.x, qA.z, qB.x, qB.z};
    float qy[4] = {qA.y, qA.w, qB.y, qB.w};
    int cnt = 4;
#pragma unroll
    for (int kk = 0; kk < 4; kk++) {
        float p1x = qx[kk], p1y = qy[kk];
        int k2 = (kk + 1) & 3;
        float ex = qx[k2] - p1x, ey = qy[k2] - p1y;
        int oc = 0;
        float d0 = ex * (py[0] - p1y) - ey * (px[0] - p1x);
        float dc = d0;
        for (int i = 0; i < cnt; i++) {
            int nx = (i + 1 < cnt) ? i + 1 : 0;
            float dn = (i + 1 < cnt) ? (ex * (py[i + 1] - p1y) - ey * (px[i + 1] - p1x)) : d0;
            bool ci = dc >= 0.f, ni = dn >= 0.f;
            if (ci) { ox[oc] = px[i]; oy[oc] = py[i]; oc++; }
            if (ci != ni) {
                float den = dc - dn;
                float tt = dc / ((den == 0.f) ? 1.f : den);
                ox[oc] = px[i] + tt * (px[nx] - px[i]);
                oy[oc] = py[i] + tt * (py[nx] - py[i]);
                oc++;
            }
            dc = dn;
        }
        cnt = oc;
        if (cnt == 0) break;
        for (int i = 0; i < cnt; i++) { px[i] = ox[i]; py[i] = oy[i]; }
    }
    if (cnt < 3) return 0.f;
    float s = 0.f;
    for (int i = 0; i < cnt; i++) {
        int nx = (i + 1 < cnt) ? i + 1 : 0;
        s += px[i] * py[nx] - px[nx] * py[i];
    }
    return 0.5f * fabsf(s);
}

// =================== the whole pipeline in ONE kernel ======================
__global__ __launch_bounds__(NT) void rpn_kernel(
    const float* __restrict__ o0, const float* __restrict__ o1,
    const float* __restrict__ o2, const float* __restrict__ o3,
    const float* __restrict__ d0, const float* __restrict__ d1,
    const float* __restrict__ d2, const float* __restrict__ d3,
    const float* __restrict__ anchors, float* __restrict__ out)
{
    __shared__ __align__(16) unsigned char s_buf[32768];  // hist / sort keys / mask tiles
    __shared__ int s_part[NT];
    __shared__ unsigned s_th;
    __shared__ int s_keep[PRE];
    __shared__ int s_n;

    int tid = threadIdx.x;
    int b, lvl, c0, n;
    map_block(blockIdx.x, b, lvl, c0, n);
    const float* obase = lvl == 0 ? o0 : lvl == 1 ? o1 : lvl == 2 ? o2 : o3;
    int H = 256 >> lvl, HW = H * H;
    int NL = 3 * HW;
    int seg4 = b * 4 + lvl;
    const float4* p4 = (const float4*)(obase + (long long)b * NL + c0);
    int n4 = n >> 2;

    // ============ stage A: histogram ============
    {
        int* h = (int*)s_buf;
        for (int i = tid; i < NBIN; i += NT) h[i] = 0;
        __syncthreads();
        for (int m = tid; m < n4; m += 2 * NT) {
            float4 v1 = p4[m];
            bool has2 = (m + NT) < n4;            // uniform per warp (sizes are warp-multiples)
            float4 v2;
            if (has2) v2 = p4[m + NT];
            hist_add(h, fflip(v1.x) >> 19);
            hist_add(h, fflip(v1.y) >> 19);
            hist_add(h, fflip(v1.z) >> 19);
            hist_add(h, fflip(v1.w) >> 19);
            if (has2) {
                hist_add(h, fflip(v2.x) >> 19);
                hist_add(h, fflip(v2.y) >> 19);
                hist_add(h, fflip(v2.z) >> 19);
                hist_add(h, fflip(v2.w) >> 19);
            }
        }
        __syncthreads();
        for (int i = tid; i < NBIN; i += NT)
            if (h[i]) atomicAdd(&g_hist[seg4][i], h[i]);
    }
    grid_bar();

    // ============ stage A2: threshold + collect ============
    {
        int s = 0;
#pragma unroll 4
        for (int k = 0; k < 16; k++)
            s += __ldcg(&g_hist[seg4][NBIN - 1 - tid * 16 - k]);
        s_part[tid] = s;
        __syncthreads();
        if (tid == 0) {
            int cum = 0, th = 0;
            for (int c = 0; c < NT; c++) {
                if (cum + s_part[c] >= PRE) {
                    int c2 = cum;
                    for (int k = 0; k < 16; k++) {
                        int bin = NBIN - 1 - c * 16 - k;
                        c2 += __ldcg(&g_hist[seg4][bin]);
                        if (c2 >= PRE) { th = bin; break; }
                    }
                    break;
                }
                cum += s_part[c];
            }
            s_th = (unsigned)th;
        }
        __syncthreads();
        unsigned th = s_th;
        for (int m = tid; m < n4; m += 2 * NT) {
            float4 v1 = p4[m];
            bool has2 = (m + NT) < n4;
            float4 v2;
            if (has2) v2 = p4[m + NT];
#pragma unroll
            for (int half = 0; half < 2; half++) {
                if (half == 1 && !has2) break;
                float4 v = half ? v2 : v1;
                int mm = half ? m + NT : m;
                float vals[4] = {v.x, v.y, v.z, v.w};
#pragma unroll
                for (int s = 0; s < 4; s++) {
                    unsigned u = fflip(vals[s]);
                    if ((u >> 19) >= th) {
                        int gm = c0 + mm * 4 + s;
                        int idx = (gm % HW) * 3 + gm / HW;   // (y*W+x)*A + a order
                        int pos = atomicAdd(&g_ccnt[seg4], 1);
                        if (pos < CANDCAP)
                            g_cand[seg4][pos] = (((unsigned long long)u) << 32) | (unsigned)(~idx);
                    }
                }
            }
        }
    }
    grid_bar();

    // ============ stage B: per-segment sort -> exact top-512 -> decode =====
    if (blockIdx.x < 16) {
        int seg = blockIdx.x;
        int sb = seg >> 2, slvl = seg & 3;
        unsigned long long* sk = (unsigned long long*)s_buf;
        int cnt = __ldcg(&g_ccnt[seg]);
        if (cnt > CANDCAP) cnt = CANDCAP;
        int M = (cnt <= 1024) ? 1024 : CANDCAP;
        for (int i = tid; i < M; i += NT)
            sk[i] = (i < cnt) ? __ldcg(&g_cand[seg][i]) : 0ull;
        __syncthreads();
        // re-zero scratch for next replay
        if (tid == 0) g_ccnt[seg] = 0;
        for (int i = tid; i < NBIN; i += NT) g_hist[seg][i] = 0;
        for (int ksz = 2; ksz <= M; ksz <<= 1) {
            for (int j = ksz >> 1; j > 0; j >>= 1) {
                for (int i = tid; i < M; i += NT) {
                    int l = i ^ j;
                    if (l > i) {
                        unsigned long long a = sk[i], c = sk[l];
                        bool desc = ((i & ksz) == 0);
                        if (desc ? (a < c) : (a > c)) { sk[i] = c; sk[l] = a; }
                    }
                }
                __syncthreads();
            }
        }
        // decode the top-512 (each of the 512 threads takes one)
        {
            unsigned long long kk = sk[tid];
            float val = funflip((unsigned)(kk >> 32));
            int li = (int)(~(unsigned)(kk & 0xFFFFFFFFull));
            int sH = 256 >> slvl, sHW = sH * sH;
            int a = li % 3, cell = li / 3;
            int x = cell % sH, y = cell / sH;
            const float* dl = slvl == 0 ? d0 : slvl == 1 ? d1 : slvl == 2 ? d2 : d3;
            long long bi = ((long long)sb * 18 + a * 6) * sHW + (long long)y * sH + x;
            float dx = dl[bi], dy = dl[bi + sHW], dw = dl[bi + 2LL * sHW],
                  dh = dl[bi + 3LL * sHW], ds = dl[bi + 4LL * sHW], dc = dl[bi + 5LL * sHW];
            int ta = c_aoff[slvl] + li;
            const float* an = anchors + ((long long)sb * TANCH + ta) * 5;
            float ax = an[0], ay = an[1], aw = an[2], ah = an[3], aa = an[4];
            const float LOGM = 4.135166556742356f;
            dw = fminf(dw, LOGM);
            dh = fminf(dh, LOGM);
            float bw = aw * expf(dw), bh = ah * expf(dh);
            float bcx = ax + dx * aw, bcy = ay + dy * ah;
            float ang = aa + atan2f(ds, dc);
            float sc = 0.5f + 0.5f * tanhf(0.5f * val);   // XLA logistic form
            bool vd = (bw >= 1e-3f) && (bh >= 1e-3f) && (sc >= 0.0f);
            int pos = slvl * PRE + tid;
            g_box[sb][pos][0] = bcx; g_box[sb][pos][1] = bcy;
            g_box[sb][pos][2] = bw;  g_box[sb][pos][3] = bh;
            g_box[sb][pos][4] = ang;
            g_score[sb][pos] = sc;
            g_valid[sb][pos] = vd ? 1 : 0;
            unsigned u = vd ? __float_as_uint(sc) : 0u;   // score desc, pos asc tiebreak
            g_key[sb][pos] = (((unsigned long long)u) << 32) | (unsigned)(2047 - pos);
        }
    }
    grid_bar();

    // ============ stage C: per-image sort + geometry ============
    if (blockIdx.x < NB) {
        int ib = blockIdx.x;
        unsigned long long* sk = (unsigned long long*)s_buf;
        for (int i = tid; i < NC; i += NT) sk[i] = __ldcg(&g_key[ib][i]);
        __syncthreads();
        for (int ksz = 2; ksz <= NC; ksz <<= 1) {
            for (int j = ksz >> 1; j > 0; j >>= 1) {
                for (int i = tid; i < NC; i += NT) {
                    int l = i ^ j;
                    if (l > i) {
                        unsigned long long a = sk[i], c = sk[l];
                        bool desc = ((i & ksz) == 0);
                        if (desc ? (a < c) : (a > c)) { sk[i] = c; sk[l] = a; }
                    }
                }
                __syncthreads();
            }
        }
        for (int i = tid; i < NC; i += NT) {
            int pos = 2047 - (int)(unsigned)(sk[i] & 0xFFFFFFFFull);
            int plvl = pos >> 9;
            float b0 = __ldcg(&g_box[ib][pos][0]), b1 = __ldcg(&g_box[ib][pos][1]);
            float w = __ldcg(&g_box[ib][pos][2]), h = __ldcg(&g_box[ib][pos][3]);
            float ang = __ldcg(&g_box[ib][pos][4]);
            g_sbox[ib][i][0] = b0; g_sbox[ib][i][1] = b1;
            g_sbox[ib][i][2] = w;  g_sbox[ib][i][3] = h;  g_sbox[ib][i][4] = ang;
            unsigned char vd = __ldcg(&g_valid[ib][pos]);
            g_svalid[ib][i] = vd;
            g_sscore[ib][i] = vd ? __ldcg(&g_score[ib][pos]) : __int_as_float(0xff800000);
            float off = 8192.0f * (float)plvl;
            float cx = b0 + off, cy = b1 + off;
            float ca = cosf(ang), sa = sinf(ang);
            float hw = 0.5f * w, hh = 0.5f * h;
            float dxs[4] = {hw, -hw, -hw, hw};
            float dys[4] = {hh, hh, -hh, -hh};
            float xmn = 1e30f, xmx = -1e30f, ymn = 1e30f, ymx = -1e30f;
#pragma unroll
            for (int c = 0; c < 4; c++) {
                float xx = cx + dxs[c] * ca - dys[c] * sa;
                float yy = cy + dxs[c] * sa + dys[c] * ca;
                g_geom[ib][i][2 * c] = xx;
                g_geom[ib][i][2 * c + 1] = yy;
                xmn = fminf(xmn, xx); xmx = fmaxf(xmx, xx);
                ymn = fminf(ymn, yy); ymx = fmaxf(ymx, yy);
            }
            g_geom[ib][i][8] = w * h;
            g_geom[ib][i][9] = cx;
            g_geom[ib][i][10] = cy;
            g_geom[ib][i][11] = 0.5f * sqrtf(w * w + h * h);
            g_geom[ib][i][12] = xmn;
            g_geom[ib][i][13] = xmx;
            g_geom[ib][i][14] = ymn;
            g_geom[ib][i][15] = ymx;
        }
    }
    grid_bar();

    // ============ stage D: rotated IoU suppression bitmask ============
    // 2112 tiles = 4 images x 528 upper-tri (rb,cb) tiles; 8 tile-groups of
    // 64 threads per block, 2 rounds.
    {
        float4* sg = (float4*)s_buf;              // [8 groups][64 boxes][4 float4]
        int grp = tid >> 6, lane = tid & 63;
#pragma unroll
        for (int round = 0; round < 2; round++) {
            int tile = blockIdx.x * 16 + round * 8 + grp;
            int img = tile / 528;
            int tri = tile % 528;
            int rb = 0, rowrem = 32;
            while (tri >= rowrem) { tri -= rowrem; rowrem--; rb++; }
            int cb = rb + tri;
            const float4* gg = (const float4*)&g_geom[img][0][0];
            __syncthreads();
            for (int i = lane; i < 256; i += 64)
                sg[grp * 256 + i] = gg[cb * 256 + i];
            __syncthreads();
            int row = rb * 64 + lane;
            float4 rA = gg[row * 4 + 0];
            float4 rB = gg[row * 4 + 1];
            float4 rC = gg[row * 4 + 2];   // area, cx, cy, r
            float4 rD = gg[row * 4 + 3];   // xmin, xmax, ymin, ymax
            unsigned long long bits = 0;
            int j0 = (cb == rb) ? lane + 1 : 0;
            for (int j = j0; j < 64; j++) {
                float4 cC = sg[grp * 256 + j * 4 + 2];
                float ddx = rC.y - cC.y, ddy = rC.z - cC.z;
                float rr = rC.w + cC.w;
                if (ddx * ddx + ddy * ddy >= rr * rr) continue;     // disjoint
                float ai = rC.x, aj = cC.x;
                float S = ai + aj;
                float mn = fminf(ai, aj), mx = fmaxf(ai, aj);
                if (mn <= 0.7f * mx) continue;                      // area-ratio bound
                float4 cD = sg[grp * 256 + j * 4 + 3];
                float xl = fmaxf(rD.x, cD.x), xr = fminf(rD.y, cD.y);
                float yl = fmaxf(rD.z, cD.z), yr = fminf(rD.w, cD.w);
                float ub = fmaxf(xr - xl, 0.f) * fmaxf(yr - yl, 0.f);
                if (ub * 1.7f < S * 0.6993f) continue;              // AABB bound (margin)
                float inter = inter_area(rA, rB, sg[grp * 256 + j * 4 + 0],
                                         sg[grp * 256 + j * 4 + 1]);
                float iou = inter / (S - inter + 1e-7f);
                if (iou > 0.7f) bits |= (1ull << j);
            }
            g_mask[img][row][cb] = bits;
        }
    }
    grid_bar();

    // ============ stage E: greedy scan + padded output ============
    if (blockIdx.x < NB) {
        int ib = blockIdx.x;
        if (tid < 32) {
            int lane = tid;
            unsigned long long remv = 0;
            const unsigned long long* vp =
                (const unsigned long long*)&g_svalid[ib][lane * 64];
#pragma unroll
            for (int q = 0; q < 8; q++) {
                unsigned long long w8 = vp[q];
#pragma unroll
                for (int kk = 0; kk < 8; kk++)
                    if (((w8 >> (kk * 8)) & 0xffull) == 0ull)
                        remv |= (1ull << (q * 8 + kk));
            }
            int nn = 0;
            unsigned long long nextw = __ldcg(&g_mask[ib][0][lane]);
            for (int i = 0; i < NC; i++) {
                unsigned long long cur = nextw;
                if (i + 1 < NC) nextw = __ldcg(&g_mask[ib][i + 1][lane]);
                unsigned long long w = __shfl_sync(0xffffffffu, remv, (i >> 6));
                if (!((w >> (i & 63)) & 1ull)) {
                    if (lane == 0) s_keep[nn] = i;
                    nn++;
                    remv |= cur;
                    if (nn >= PRE) break;
                }
            }
            if (lane == 0) s_n = nn;
        }
        __syncthreads();
        int nn = s_n;
        float v0 = 0, v1 = 0, v2 = 0, v3 = 0, v4 = 0, sc = 0;
        if (tid < nn) {
            int i = s_keep[tid];
            v0 = g_sbox[ib][i][0]; v1 = g_sbox[ib][i][1];
            v2 = g_sbox[ib][i][2]; v3 = g_sbox[ib][i][3];
            v4 = g_sbox[ib][i][4];
            sc = g_sscore[ib][i];
        }
        float* ob = out + ((long long)ib * PRE + tid) * 5;
        ob[0] = v0; ob[1] = v1; ob[2] = v2; ob[3] = v3; ob[4] = v4;
        out[NB * PRE * 5 + ib * PRE + tid] = sc;
    }
}

extern "C" void kernel_launch(void* const* d_in, const int* in_sizes, int n_in,
                              void* d_out, int out_size) {
    const float* obj[4] = {0, 0, 0, 0};
    const float* dlt[4] = {0, 0, 0, 0};
    const float* anch = 0;
    const int osz[4] = {786432, 196608, 49152, 12288};
    const int dsz[4] = {4718592, 1179648, 294912, 73728};
    for (int i = 0; i < n_in; i++) {
        int s = in_sizes[i];
        const float* p = (const float*)d_in[i];
        if (s == 5222400) { anch = p; continue; }
        for (int l = 0; l < 4; l++) {
            if (s == osz[l]) obj[l] = p;
            else if (s == dsz[l]) dlt[l] = p;
        }
    }
    rpn_kernel<<<NBLK, NT>>>(obj[0], obj[1], obj[2], obj[3],
                             dlt[0], dlt[1], dlt[2], dlt[3],
                             anch, (float*)d_out);
}

// round 5
// speedup vs baseline: 1.1798x; 1.1798x over previous
#include <cuda_runtime.h>

#define NB 4
#define PRE 512
#define NC 2048
#define TANCH 261120
#define NBIN 8192
#define CANDCAP 2048
#define NBLK 132

// ---------------- scratch (device globals; zero-initialized) --------------
__device__ int g_hist[16][NBIN];
__device__ int g_ccnt[16];
__device__ int g_sync;
__device__ unsigned long long g_cand[16][CANDCAP];
__device__ float g_box[NB][NC][5];
__device__ float g_score[NB][NC];
__device__ unsigned char g_valid[NB][NC];
__device__ unsigned long long g_key[NB][NC];
__device__ float g_sbox[NB][NC][5];
__device__ float g_sscore[NB][NC];
__device__ unsigned char g_svalid[NB][NC];
__device__ float g_geom[NB][NC][16];   // x0..y3, area, cx, cy, r, xmin,xmax,ymin,ymax
__device__ unsigned long long g_mask[NB][NC][32];

__device__ const int c_aoff[4] = {0, 196608, 245760, 258048};

__device__ __forceinline__ unsigned fflip(float f) {
    unsigned u = __float_as_uint(f);
    return (u & 0x80000000u) ? ~u : (u | 0x80000000u);
}
__device__ __forceinline__ float funflip(unsigned u) {
    return __uint_as_float((u & 0x80000000u) ? (u ^ 0x80000000u) : ~u);
}

// block mapping: 33 blocks per image
__device__ __forceinline__ void map_block(int bx, int& b, int& lvl, int& c0, int& n) {
    b = bx / 33;
    int t = bx % 33;
    if (t < 24)      { lvl = 0; c0 = t * 8192;        n = 8192; }
    else if (t < 30) { lvl = 1; c0 = (t - 24) * 8192; n = 8192; }
    else if (t < 32) { lvl = 2; c0 = (t - 30) * 6144; n = 6144; }
    else             { lvl = 3; c0 = 0;               n = 3072; }
}

__device__ __forceinline__ void hist_add(int* h, unsigned bin) {
    unsigned m = __match_any_sync(0xffffffffu, bin);
    int leader = __ffs(m) - 1;
    if ((threadIdx.x & 31) == leader) atomicAdd(&h[bin], __popc(m));
}

// ------------- stage 1 (fused): hist -> grid barrier -> thresh -> collect --
__global__ __launch_bounds__(256) void select_kernel(const float* __restrict__ o0,
                                                     const float* __restrict__ o1,
                                                     const float* __restrict__ o2,
                                                     const float* __restrict__ o3) {
    __shared__ int h[NBIN];
    for (int i = threadIdx.x; i < NBIN; i += 256) h[i] = 0;
    __syncthreads();
    int b, lvl, c0, n;
    map_block(blockIdx.x, b, lvl, c0, n);
    const float* base = lvl == 0 ? o0 : lvl == 1 ? o1 : lvl == 2 ? o2 : o3;
    int H = 256 >> lvl, HW = H * H;
    int NL = 3 * HW;
    int seg = b * 4 + lvl;
    const float4* p4 = (const float4*)(base + (long long)b * NL + c0);
    int n4 = n >> 2;

    for (int m = threadIdx.x; m < n4; m += 256) {
        float4 v = p4[m];
        hist_add(h, fflip(v.x) >> 19);
        hist_add(h, fflip(v.y) >> 19);
        hist_add(h, fflip(v.z) >> 19);
        hist_add(h, fflip(v.w) >> 19);
    }
    __syncthreads();
    for (int i = threadIdx.x; i < NBIN; i += 256)
        if (h[i]) atomicAdd(&g_hist[seg][i], h[i]);

    // grid barrier (all 132 blocks co-resident)
    __syncthreads();
    if (threadIdx.x == 0) {
        __threadfence();
        atomicAdd(&g_sync, 1);
        while (atomicAdd(&g_sync, 0) < NBLK) {}
        __threadfence();
    }
    __syncthreads();

    __shared__ int part[256];
    __shared__ unsigned s_th;
    {
        int t = threadIdx.x;
        int s = 0;
#pragma unroll 4
        for (int k = 0; k < 32; k++)
            s += __ldcg(&g_hist[seg][NBIN - 1 - t * 32 - k]);
        part[t] = s;
    }
    __syncthreads();
    if (threadIdx.x == 0) {
        int cum = 0, th = 0;
        for (int c = 0; c < 256; c++) {
            if (cum + part[c] >= PRE) {
                int c2 = cum;
                for (int k = 0; k < 32; k++) {
                    int bin = NBIN - 1 - c * 32 - k;
                    c2 += __ldcg(&g_hist[seg][bin]);
                    if (c2 >= PRE) { th = bin; break; }
                }
                break;
            }
            cum += part[c];
        }
        s_th = (unsigned)th;
    }
    __syncthreads();
    unsigned th = s_th;

    for (int m = threadIdx.x; m < n4; m += 256) {
        float4 v = p4[m];
        float vals[4] = {v.x, v.y, v.z, v.w};
#pragma unroll
        for (int s = 0; s < 4; s++) {
            unsigned u = fflip(vals[s]);
            if ((u >> 19) >= th) {
                int gm = c0 + m * 4 + s;
                int idx = (gm % HW) * 3 + gm / HW;   // (y*W+x)*A + a order
                int pos = atomicAdd(&g_ccnt[seg], 1);
                if (pos < CANDCAP)
                    g_cand[seg][pos] = (((unsigned long long)u) << 32) | (unsigned)(~idx);
            }
        }
    }
}

// ------- stage 2: per-segment sort -> exact top-512 -> decode --------------
// After decode, a stable compaction pushes invalid entries to the run tail so
// each level's 512-run in g_key is strictly descending (merge-ready) while
// preserving the reference's stable (score desc, original-position asc) order.
__global__ __launch_bounds__(512) void sortdecode_kernel(const float* __restrict__ d0,
                                                         const float* __restrict__ d1,
                                                         const float* __restrict__ d2,
                                                         const float* __restrict__ d3,
                                                         const float* __restrict__ anchors) {
    int seg = blockIdx.x;
    int sb = seg >> 2, slvl = seg & 3;
    __shared__ unsigned long long sk[CANDCAP];
    __shared__ int wtot[16], woff[16];
    __shared__ int s_tot;
    int tid = threadIdx.x;
    int cnt = g_ccnt[seg];
    if (cnt > CANDCAP) cnt = CANDCAP;
    int M = (cnt <= 1024) ? 1024 : CANDCAP;
    for (int i = tid; i < M; i += 512)
        sk[i] = (i < cnt) ? g_cand[seg][i] : 0ull;
    __syncthreads();
    // re-zero scratch for next replay
    if (tid == 0) {
        g_ccnt[seg] = 0;
        if (seg == 0) g_sync = 0;
    }
    for (int i = tid; i < NBIN; i += 512) g_hist[seg][i] = 0;
    for (int ksz = 2; ksz <= M; ksz <<= 1) {
        for (int j = ksz >> 1; j > 0; j >>= 1) {
            for (int i = tid; i < M; i += 512) {
                int l = i ^ j;
                if (l > i) {
                    unsigned long long a = sk[i], c = sk[l];
                    bool desc = ((i & ksz) == 0);
                    if (desc ? (a < c) : (a > c)) { sk[i] = c; sk[l] = a; }
                }
            }
            __syncthreads();
        }
    }
    // decode (each of the 512 threads takes one entry)
    unsigned long long kk = sk[tid];
    float val = funflip((unsigned)(kk >> 32));
    int li = (int)(~(unsigned)(kk & 0xFFFFFFFFull));
    int sH = 256 >> slvl, sHW = sH * sH;
    int a = li % 3, cell = li / 3;
    int x = cell % sH, y = cell / sH;
    const float* dl = slvl == 0 ? d0 : slvl == 1 ? d1 : slvl == 2 ? d2 : d3;
    long long bi = ((long long)sb * 18 + a * 6) * sHW + (long long)y * sH + x;
    float dx = dl[bi], dy = dl[bi + sHW], dw = dl[bi + 2LL * sHW],
          dh = dl[bi + 3LL * sHW], ds = dl[bi + 4LL * sHW], dc = dl[bi + 5LL * sHW];
    int ta = c_aoff[slvl] + li;
    const float* an = anchors + ((long long)sb * TANCH + ta) * 5;
    float ax = an[0], ay = an[1], aw = an[2], ah = an[3], aa = an[4];
    const float LOGM = 4.135166556742356f;
    dw = fminf(dw, LOGM);
    dh = fminf(dh, LOGM);
    float bw = aw * expf(dw), bh = ah * expf(dh);
    float bcx = ax + dx * aw, bcy = ay + dy * ah;
    float ang = aa + atan2f(ds, dc);
    float sc = 0.5f + 0.5f * tanhf(0.5f * val);       // XLA logistic form
    bool vd = (bw >= 1e-3f) && (bh >= 1e-3f) && (sc >= 0.0f);

    // stable compaction: valids keep order at front, invalids (score -inf in
    // reference) keep order at tail. rank preserves t-order in both classes.
    unsigned bal = __ballot_sync(0xffffffffu, vd);
    int lane = tid & 31, w = tid >> 5;
    int prew = __popc(bal & ((1u << lane) - 1u));
    if (lane == 0) wtot[w] = __popc(bal);
    __syncthreads();
    if (tid == 0) {
        int s = 0;
        for (int q = 0; q < 16; q++) { woff[q] = s; s += wtot[q]; }
        s_tot = s;
    }
    __syncthreads();
    int vbefore = woff[w] + prew;
    int rank = vd ? vbefore : (s_tot + (tid - vbefore));
    int pos = slvl * PRE + rank;

    g_box[sb][pos][0] = bcx; g_box[sb][pos][1] = bcy;
    g_box[sb][pos][2] = bw;  g_box[sb][pos][3] = bh;
    g_box[sb][pos][4] = ang;
    g_score[sb][pos] = sc;
    g_valid[sb][pos] = vd ? 1 : 0;
    unsigned u = vd ? __float_as_uint(sc) : 0u;       // score desc, pos asc tiebreak
    g_key[sb][pos] = (((unsigned long long)u) << 32) | (unsigned)(2047 - pos);
}

// -------- stage 3: 4-way merge of sorted runs + geometry (no bitonic) ------
__device__ __forceinline__ unsigned long long merge_pick(
    const unsigned long long* A, const unsigned long long* B, int len, int i) {
    int lo = i > len ? i - len : 0;
    int hi = i < len ? i : len;
    while (lo < hi) {
        int a = (lo + hi) >> 1;
        if (A[a] > B[i - a - 1]) lo = a + 1; else hi = a;
    }
    int aa = lo, bb = i - lo;
    return (aa < len && (bb >= len || A[aa] > B[bb])) ? A[aa] : B[bb];
}

__global__ __launch_bounds__(512) void geom_kernel() {
    int b = blockIdx.x;
    __shared__ unsigned long long sk[NC];
    __shared__ unsigned long long tmp[NC];
    int tid = threadIdx.x;
    for (int i = tid; i < NC; i += 512) sk[i] = g_key[b][i];
    __syncthreads();
    // merge level runs (each 512, strictly descending, unique keys)
#pragma unroll
    for (int half = 0; half < 2; half++) {
        const unsigned long long* A = sk + half * 1024;
        for (int i = tid; i < 1024; i += 512)
            tmp[half * 1024 + i] = merge_pick(A, A + 512, 512, i);
    }
    __syncthreads();
    for (int i = tid; i < 2048; i += 512)
        sk[i] = merge_pick(tmp, tmp + 1024, 1024, i);
    __syncthreads();

    for (int i = tid; i < NC; i += 512) {
        int pos = 2047 - (int)(unsigned)(sk[i] & 0xFFFFFFFFull);
        int plvl = pos >> 9;
        float b0 = g_box[b][pos][0], b1 = g_box[b][pos][1];
        float w = g_box[b][pos][2], h = g_box[b][pos][3], ang = g_box[b][pos][4];
        g_sbox[b][i][0] = b0; g_sbox[b][i][1] = b1;
        g_sbox[b][i][2] = w;  g_sbox[b][i][3] = h;  g_sbox[b][i][4] = ang;
        unsigned char vd = g_valid[b][pos];
        g_svalid[b][i] = vd;
        g_sscore[b][i] = vd ? g_score[b][pos] : __int_as_float(0xff800000);
        float off = 8192.0f * (float)plvl;
        float cx = b0 + off, cy = b1 + off;
        float ca = cosf(ang), sa = sinf(ang);
        float hw = 0.5f * w, hh = 0.5f * h;
        float dxs[4] = {hw, -hw, -hw, hw};
        float dys[4] = {hh, hh, -hh, -hh};
        float xmn = 1e30f, xmx = -1e30f, ymn = 1e30f, ymx = -1e30f;
#pragma unroll
        for (int c = 0; c < 4; c++) {
            float xx = cx + dxs[c] * ca - dys[c] * sa;
            float yy = cy + dxs[c] * sa + dys[c] * ca;
            g_geom[b][i][2 * c] = xx;
            g_geom[b][i][2 * c + 1] = yy;
            xmn = fminf(xmn, xx); xmx = fmaxf(xmx, xx);
            ymn = fminf(ymn, yy); ymx = fmaxf(ymx, yy);
        }
        g_geom[b][i][8] = w * h;
        g_geom[b][i][9] = cx;
        g_geom[b][i][10] = cy;
        g_geom[b][i][11] = 0.5f * sqrtf(w * w + h * h);
        g_geom[b][i][12] = xmn;
        g_geom[b][i][13] = xmx;
        g_geom[b][i][14] = ymn;
        g_geom[b][i][15] = ymx;
    }
}

// ---------------- stage 4: rotated IoU suppression bitmask -----------------
__device__ float inter_area(float4 pA, float4 pB, float4 qA, float4 qB) {
    float px[8], py[8], ox[8], oy[8];
    px[0] = pA.x; py[0] = pA.y; px[1] = pA.z; py[1] = pA.w;
    px[2] = pB.x; py[2] = pB.y; px[3] = pB.z; py[3] = pB.w;
    float qx[4] = {qA.x, qA.z, qB.x, qB.z};
    float qy[4] = {qA.y, qA.w, qB.y, qB.w};
    int cnt = 4;
#pragma unroll
    for (int kk = 0; kk < 4; kk++) {
        float p1x = qx[kk], p1y = qy[kk];
        int k2 = (kk + 1) & 3;
        float ex = qx[k2] - p1x, ey = qy[k2] - p1y;
        int oc = 0;
        float d0 = ex * (py[0] - p1y) - ey * (px[0] - p1x);
        float dc = d0;
        for (int i = 0; i < cnt; i++) {
            int nx = (i + 1 < cnt) ? i + 1 : 0;
            float dn = (i + 1 < cnt) ? (ex * (py[i + 1] - p1y) - ey * (px[i + 1] - p1x)) : d0;
            bool ci = dc >= 0.f, ni = dn >= 0.f;
            if (ci) { ox[oc] = px[i]; oy[oc] = py[i]; oc++; }
            if (ci != ni) {
                float den = dc - dn;
                float tt = dc / ((den == 0.f) ? 1.f : den);
                ox[oc] = px[i] + tt * (px[nx] - px[i]);
                oy[oc] = py[i] + tt * (py[nx] - py[i]);
                oc++;
            }
            dc = dn;
        }
        cnt = oc;
        if (cnt == 0) break;
        for (int i = 0; i < cnt; i++) { px[i] = ox[i]; py[i] = oy[i]; }
    }
    if (cnt < 3) return 0.f;
    float s = 0.f;
    for (int i = 0; i < cnt; i++) {
        int nx = (i + 1 < cnt) ? i + 1 : 0;
        s += px[i] * py[nx] - px[nx] * py[i];
    }
    return 0.5f * fabsf(s);
}

__global__ __launch_bounds__(256) void mask_kernel() {
    int grp = threadIdx.x >> 6, lane = threadIdx.x & 63;
    int tile = blockIdx.x * 4 + grp;            // 2112 tiles total
    int img = tile / 528, tri = tile % 528;
    int rb = 0, rowrem = 32;
    while (tri >= rowrem) { tri -= rowrem; rowrem--; rb++; }
    int cb = rb + tri;

    __shared__ float4 sg[4][64][4];
    const float4* gg = (const float4*)&g_geom[img][0][0];
    for (int i = lane; i < 256; i += 64)
        ((float4*)sg[grp])[i] = gg[cb * 256 + i];
    __syncthreads();

    int row = rb * 64 + lane;
    float4 rA = gg[row * 4 + 0];
    float4 rB = gg[row * 4 + 1];
    float4 rC = gg[row * 4 + 2];   // area, cx, cy, r
    float4 rD = gg[row * 4 + 3];   // xmin, xmax, ymin, ymax

    // pass 1: branchless cheap filters -> survivor bitmask
    unsigned long long surv = 0;
#pragma unroll 4
    for (int j = 0; j < 64; j++) {
        float4 cC = sg[grp][j][2];
        float ddx = rC.y - cC.y, ddy = rC.z - cC.z;
        float rr = rC.w + cC.w;
        float mn = fminf(rC.x, cC.x), mx = fmaxf(rC.x, cC.x);
        bool ok = (ddx * ddx + ddy * ddy < rr * rr) && (mn > 0.7f * mx);
        surv |= ((unsigned long long)ok) << j;
    }
    if (cb == rb) surv &= (lane < 63) ? (~0ull << (lane + 1)) : 0ull;

    // pass 2: exact checks only on survivors
    unsigned long long bits = 0;
    while (surv) {
        int j = __ffsll((long long)surv) - 1;
        surv &= surv - 1;
        float4 cC = sg[grp][j][2];
        float4 cD = sg[grp][j][3];
        float S = rC.x + cC.x;
        float xl = fmaxf(rD.x, cD.x), xr = fminf(rD.y, cD.y);
        float yl = fmaxf(rD.z, cD.z), yr = fminf(rD.w, cD.w);
        float ub = fmaxf(xr - xl, 0.f) * fmaxf(yr - yl, 0.f);
        if (ub * 1.7f < S * 0.6993f) continue;              // AABB bound (margin)
        float inter = inter_area(rA, rB, sg[grp][j][0], sg[grp][j][1]);
        float iou = inter / (S - inter + 1e-7f);
        if (iou > 0.7f) bits |= (1ull << j);
    }
    g_mask[img][row][cb] = bits;
}

// ---------- stage 5 (fused): greedy scan + padded output write ------------
__global__ __launch_bounds__(512) void greedy_out_kernel(float* __restrict__ out) {
    int b = blockIdx.x;
    int tid = threadIdx.x;
    __shared__ int keep[PRE];
    __shared__ int s_n;
    if (tid < 32) {
        int lane = tid;
        unsigned long long remv = 0;
        const unsigned long long* vp = (const unsigned long long*)&g_svalid[b][lane * 64];
#pragma unroll
        for (int q = 0; q < 8; q++) {
            unsigned long long w8 = vp[q];
#pragma unroll
            for (int kk = 0; kk < 8; kk++)
                if (((w8 >> (kk * 8)) & 0xffull) == 0ull)
                    remv |= (1ull << (q * 8 + kk));
        }
        int n = 0;
        unsigned long long nextw = g_mask[b][0][lane];
        for (int i = 0; i < NC; i++) {
            unsigned long long cur = nextw;
            if (i + 1 < NC) nextw = g_mask[b][i + 1][lane];   // unconditional prefetch
            unsigned long long w = __shfl_sync(0xffffffffu, remv, (i >> 6));
            if (!((w >> (i & 63)) & 1ull)) {
                if (lane == 0) keep[n] = i;
                n++;
                remv |= cur;
                if (n >= PRE) break;
            }
        }
        if (lane == 0) s_n = n;
    }
    __syncthreads();
    int n = s_n;
    float v0 = 0, v1 = 0, v2 = 0, v3 = 0, v4 = 0, sc = 0;
    if (tid < n) {
        int i = keep[tid];
        v0 = g_sbox[b][i][0]; v1 = g_sbox[b][i][1];
        v2 = g_sbox[b][i][2]; v3 = g_sbox[b][i][3];
        v4 = g_sbox[b][i][4];
        sc = g_sscore[b][i];
    }
    float* ob = out + ((long long)b * PRE + tid) * 5;
    ob[0] = v0; ob[1] = v1; ob[2] = v2; ob[3] = v3; ob[4] = v4;
    out[NB * PRE * 5 + b * PRE + tid] = sc;
}

extern "C" void kernel_launch(void* const* d_in, const int* in_sizes, int n_in,
                              void* d_out, int out_size) {
    const float* obj[4] = {0, 0, 0, 0};
    const float* dlt[4] = {0, 0, 0, 0};
    const float* anch = 0;
    const int osz[4] = {786432, 196608, 49152, 12288};
    const int dsz[4] = {4718592, 1179648, 294912, 73728};
    for (int i = 0; i < n_in; i++) {
        int s = in_sizes[i];
        const float* p = (const float*)d_in[i];
        if (s == 5222400) { anch = p; continue; }
        for (int l = 0; l < 4; l++) {
            if (s == osz[l]) obj[l] = p;
            else if (s == dsz[l]) dlt[l] = p;
        }
    }
    select_kernel<<<NBLK, 256>>>(obj[0], obj[1], obj[2], obj[3]);
    sortdecode_kernel<<<16, 512>>>(dlt[0], dlt[1], dlt[2], dlt[3], anch);
    geom_kernel<<<NB, 512>>>();
    mask_kernel<<<528, 256>>>();
    greedy_out_kernel<<<NB, 512>>>((float*)d_out);
}

// round 6
// speedup vs baseline: 1.6865x; 1.4295x over previous
#include <cuda_runtime.h>

#define NB 4
#define PRE 512
#define NC 2048
#define TANCH 261120
#define NBIN 8192
#define CANDCAP 2048
#define NBLK 132

// ---------------- scratch (device globals; zero-initialized) --------------
__device__ int g_hist[16][NBIN];
__device__ int g_ccnt[16];
__device__ int g_segarr[16];                      // per-segment barrier counters
__device__ unsigned long long g_rowany[NB][32];   // per-row "has suppression bits"
__device__ unsigned long long g_cand[16][CANDCAP];
__device__ float g_box[NB][NC][5];
__device__ float g_score[NB][NC];
__device__ unsigned char g_valid[NB][NC];
__device__ unsigned long long g_key[NB][NC];
__device__ float g_sbox[NB][NC][5];
__device__ float g_sscore[NB][NC];
__device__ unsigned char g_svalid[NB][NC];
__device__ float g_geom[NB][NC][16];   // x0..y3, area, cx, cy, r, xmin,xmax,ymin,ymax
__device__ unsigned long long g_mask[NB][NC][32];

__device__ const int c_aoff[4] = {0, 196608, 245760, 258048};
__device__ const int c_segblk[4] = {24, 6, 2, 1};   // producer blocks per level

__device__ __forceinline__ unsigned fflip(float f) {
    unsigned u = __float_as_uint(f);
    return (u & 0x80000000u) ? ~u : (u | 0x80000000u);
}
__device__ __forceinline__ float funflip(unsigned u) {
    return __uint_as_float((u & 0x80000000u) ? (u ^ 0x80000000u) : ~u);
}

// block mapping: 33 blocks per image
__device__ __forceinline__ void map_block(int bx, int& b, int& lvl, int& c0, int& n) {
    b = bx / 33;
    int t = bx % 33;
    if (t < 24)      { lvl = 0; c0 = t * 8192;        n = 8192; }
    else if (t < 30) { lvl = 1; c0 = (t - 24) * 8192; n = 8192; }
    else if (t < 32) { lvl = 2; c0 = (t - 30) * 6144; n = 6144; }
    else             { lvl = 3; c0 = 0;               n = 3072; }
}

__device__ __forceinline__ void hist_add(int* h, unsigned bin) {
    unsigned m = __match_any_sync(0xffffffffu, bin);
    int leader = __ffs(m) - 1;
    if ((threadIdx.x & 31) == leader) atomicAdd(&h[bin], __popc(m));
}

// ---------------- stage 0: tiny init (per-replay resets) ------------------
__global__ void init_kernel() {
    int t = threadIdx.x;
    if (t < 16) g_segarr[t] = 0;
    if (t < 128) ((unsigned long long*)g_rowany)[t] = 0ull;
}

// ------------- stage 1 (fused): hist -> seg barrier -> thresh -> collect ---
__global__ __launch_bounds__(256) void select_kernel(const float* __restrict__ o0,
                                                     const float* __restrict__ o1,
                                                     const float* __restrict__ o2,
                                                     const float* __restrict__ o3) {
    __shared__ int h[NBIN];
    for (int i = threadIdx.x; i < NBIN; i += 256) h[i] = 0;
    __syncthreads();
    int b, lvl, c0, n;
    map_block(blockIdx.x, b, lvl, c0, n);
    const float* base = lvl == 0 ? o0 : lvl == 1 ? o1 : lvl == 2 ? o2 : o3;
    int H = 256 >> lvl, HW = H * H;
    int NL = 3 * HW;
    int seg = b * 4 + lvl;
    const float4* p4 = (const float4*)(base + (long long)b * NL + c0);
    int n4 = n >> 2;

    for (int m = threadIdx.x; m < n4; m += 256) {
        float4 v = p4[m];
        hist_add(h, fflip(v.x) >> 19);
        hist_add(h, fflip(v.y) >> 19);
        hist_add(h, fflip(v.z) >> 19);
        hist_add(h, fflip(v.w) >> 19);
    }
    __syncthreads();
    for (int i = threadIdx.x; i < NBIN; i += 256)
        if (h[i]) atomicAdd(&g_hist[seg][i], h[i]);

    // per-segment barrier: wait only for this segment's producer blocks
    __syncthreads();
    if (threadIdx.x == 0) {
        __threadfence();
        atomicAdd(&g_segarr[seg], 1);
        int need = c_segblk[lvl];
        while (atomicAdd(&g_segarr[seg], 0) < need) {}
        __threadfence();
    }
    __syncthreads();

    // threshold: 32 bins/thread cached in registers; search is mem-light
    __shared__ int part[256];
    __shared__ int s_c, s_cum;
    __shared__ unsigned s_th;
    int loc[32];
    {
        int t = threadIdx.x;
        int s = 0;
#pragma unroll
        for (int k = 0; k < 32; k++) {
            loc[k] = __ldcg(&g_hist[seg][NBIN - 1 - t * 32 - k]);
            s += loc[k];
        }
        part[t] = s;
    }
    __syncthreads();
    if (threadIdx.x == 0) {
        int cum = 0, c = 255;
        for (int q = 0; q < 256; q++) {
            if (cum + part[q] >= PRE) { c = q; break; }
            cum += part[q];
        }
        s_c = c; s_cum = cum;
    }
    __syncthreads();
    if (threadIdx.x == s_c) {
        int c2 = s_cum, th = 0;
#pragma unroll
        for (int k = 0; k < 32; k++) {
            int bin = NBIN - 1 - threadIdx.x * 32 - k;
            c2 += loc[k];
            if (c2 >= PRE) { th = bin; break; }
        }
        s_th = (unsigned)th;
    }
    __syncthreads();
    unsigned th = s_th;

    for (int m = threadIdx.x; m < n4; m += 256) {
        float4 v = p4[m];
        float vals[4] = {v.x, v.y, v.z, v.w};
#pragma unroll
        for (int s = 0; s < 4; s++) {
            unsigned u = fflip(vals[s]);
            if ((u >> 19) >= th) {
                int gm = c0 + m * 4 + s;
                int idx = (gm % HW) * 3 + gm / HW;   // (y*W+x)*A + a order
                int pos = atomicAdd(&g_ccnt[seg], 1);
                if (pos < CANDCAP)
                    g_cand[seg][pos] = (((unsigned long long)u) << 32) | (unsigned)(~idx);
            }
        }
    }
}

// ------- stage 2: per-segment sort -> exact top-512 -> decode --------------
// Stable compaction pushes invalid entries to the run tail so each level's
// 512-run in g_key is strictly descending (merge-ready).
__global__ __launch_bounds__(512) void sortdecode_kernel(const float* __restrict__ d0,
                                                         const float* __restrict__ d1,
                                                         const float* __restrict__ d2,
                                                         const float* __restrict__ d3,
                                                         const float* __restrict__ anchors) {
    int seg = blockIdx.x;
    int sb = seg >> 2, slvl = seg & 3;
    __shared__ unsigned long long sk[CANDCAP];
    __shared__ int wtot[16], woff[16];
    __shared__ int s_tot;
    int tid = threadIdx.x;
    int cnt = g_ccnt[seg];
    if (cnt > CANDCAP) cnt = CANDCAP;
    int M = (cnt <= 1024) ? 1024 : CANDCAP;
    for (int i = tid; i < M; i += 512)
        sk[i] = (i < cnt) ? g_cand[seg][i] : 0ull;
    __syncthreads();
    // re-zero scratch for next replay
    if (tid == 0) g_ccnt[seg] = 0;
    for (int i = tid; i < NBIN; i += 512) g_hist[seg][i] = 0;
    for (int ksz = 2; ksz <= M; ksz <<= 1) {
        for (int j = ksz >> 1; j > 0; j >>= 1) {
            for (int i = tid; i < M; i += 512) {
                int l = i ^ j;
                if (l > i) {
                    unsigned long long a = sk[i], c = sk[l];
                    bool desc = ((i & ksz) == 0);
                    if (desc ? (a < c) : (a > c)) { sk[i] = c; sk[l] = a; }
                }
            }
            __syncthreads();
        }
    }
    // decode (each of the 512 threads takes one entry)
    unsigned long long kk = sk[tid];
    float val = funflip((unsigned)(kk >> 32));
    int li = (int)(~(unsigned)(kk & 0xFFFFFFFFull));
    int sH = 256 >> slvl, sHW = sH * sH;
    int a = li % 3, cell = li / 3;
    int x = cell % sH, y = cell / sH;
    const float* dl = slvl == 0 ? d0 : slvl == 1 ? d1 : slvl == 2 ? d2 : d3;
    long long bi = ((long long)sb * 18 + a * 6) * sHW + (long long)y * sH + x;
    float dx = dl[bi], dy = dl[bi + sHW], dw = dl[bi + 2LL * sHW],
          dh = dl[bi + 3LL * sHW], ds = dl[bi + 4LL * sHW], dc = dl[bi + 5LL * sHW];
    int ta = c_aoff[slvl] + li;
    const float* an = anchors + ((long long)sb * TANCH + ta) * 5;
    float ax = an[0], ay = an[1], aw = an[2], ah = an[3], aa = an[4];
    const float LOGM = 4.135166556742356f;
    dw = fminf(dw, LOGM);
    dh = fminf(dh, LOGM);
    float bw = aw * expf(dw), bh = ah * expf(dh);
    float bcx = ax + dx * aw, bcy = ay + dy * ah;
    float ang = aa + atan2f(ds, dc);
    float sc = 0.5f + 0.5f * tanhf(0.5f * val);       // XLA logistic form
    bool vd = (bw >= 1e-3f) && (bh >= 1e-3f) && (sc >= 0.0f);

    // stable compaction: valids to front, invalids to tail, order preserved
    unsigned bal = __ballot_sync(0xffffffffu, vd);
    int lane = tid & 31, w = tid >> 5;
    int prew = __popc(bal & ((1u << lane) - 1u));
    if (lane == 0) wtot[w] = __popc(bal);
    __syncthreads();
    if (tid == 0) {
        int s = 0;
        for (int q = 0; q < 16; q++) { woff[q] = s; s += wtot[q]; }
        s_tot = s;
    }
    __syncthreads();
    int vbefore = woff[w] + prew;
    int rank = vd ? vbefore : (s_tot + (tid - vbefore));
    int pos = slvl * PRE + rank;

    g_box[sb][pos][0] = bcx; g_box[sb][pos][1] = bcy;
    g_box[sb][pos][2] = bw;  g_box[sb][pos][3] = bh;
    g_box[sb][pos][4] = ang;
    g_score[sb][pos] = sc;
    g_valid[sb][pos] = vd ? 1 : 0;
    unsigned u = vd ? __float_as_uint(sc) : 0u;       // score desc, pos asc tiebreak
    g_key[sb][pos] = (((unsigned long long)u) << 32) | (unsigned)(2047 - pos);
}

// -------- stage 3: 4-way merge of sorted runs + geometry -------------------
__device__ __forceinline__ unsigned long long merge_pick(
    const unsigned long long* A, const unsigned long long* B, int len, int i) {
    int lo = i > len ? i - len : 0;
    int hi = i < len ? i : len;
    while (lo < hi) {
        int a = (lo + hi) >> 1;
        if (A[a] > B[i - a - 1]) lo = a + 1; else hi = a;
    }
    int aa = lo, bb = i - lo;
    return (aa < len && (bb >= len || A[aa] > B[bb])) ? A[aa] : B[bb];
}

__global__ __launch_bounds__(512) void geom_kernel() {
    int b = blockIdx.x;
    __shared__ unsigned long long sk[NC];
    __shared__ unsigned long long tmp[NC];
    int tid = threadIdx.x;
    for (int i = tid; i < NC; i += 512) sk[i] = g_key[b][i];
    __syncthreads();
#pragma unroll
    for (int half = 0; half < 2; half++) {
        const unsigned long long* A = sk + half * 1024;
        for (int i = tid; i < 1024; i += 512)
            tmp[half * 1024 + i] = merge_pick(A, A + 512, 512, i);
    }
    __syncthreads();
    for (int i = tid; i < 2048; i += 512)
        sk[i] = merge_pick(tmp, tmp + 1024, 1024, i);
    __syncthreads();

    for (int i = tid; i < NC; i += 512) {
        int pos = 2047 - (int)(unsigned)(sk[i] & 0xFFFFFFFFull);
        int plvl = pos >> 9;
        float b0 = g_box[b][pos][0], b1 = g_box[b][pos][1];
        float w = g_box[b][pos][2], h = g_box[b][pos][3], ang = g_box[b][pos][4];
        g_sbox[b][i][0] = b0; g_sbox[b][i][1] = b1;
        g_sbox[b][i][2] = w;  g_sbox[b][i][3] = h;  g_sbox[b][i][4] = ang;
        unsigned char vd = g_valid[b][pos];
        g_svalid[b][i] = vd;
        g_sscore[b][i] = vd ? g_score[b][pos] : __int_as_float(0xff800000);
        float off = 8192.0f * (float)plvl;
        float cx = b0 + off, cy = b1 + off;
        float ca = cosf(ang), sa = sinf(ang);
        float hw = 0.5f * w, hh = 0.5f * h;
        float dxs[4] = {hw, -hw, -hw, hw};
        float dys[4] = {hh, hh, -hh, -hh};
        float xmn = 1e30f, xmx = -1e30f, ymn = 1e30f, ymx = -1e30f;
#pragma unroll
        for (int c = 0; c < 4; c++) {
            float xx = cx + dxs[c] * ca - dys[c] * sa;
            float yy = cy + dxs[c] * sa + dys[c] * ca;
            g_geom[b][i][2 * c] = xx;
            g_geom[b][i][2 * c + 1] = yy;
            xmn = fminf(xmn, xx); xmx = fmaxf(xmx, xx);
            ymn = fminf(ymn, yy); ymx = fmaxf(ymx, yy);
        }
        g_geom[b][i][8] = w * h;
        g_geom[b][i][9] = cx;
        g_geom[b][i][10] = cy;
        g_geom[b][i][11] = 0.5f * sqrtf(w * w + h * h);
        g_geom[b][i][12] = xmn;
        g_geom[b][i][13] = xmx;
        g_geom[b][i][14] = ymn;
        g_geom[b][i][15] = ymx;
    }
}

// ---------------- stage 4: rotated IoU suppression bitmask -----------------
__device__ float inter_area(float4 pA, float4 pB, float4 qA, float4 qB) {
    float px[8], py[8], ox[8], oy[8];
    px[0] = pA.x; py[0] = pA.y; px[1] = pA.z; py[1] = pA.w;
    px[2] = pB.x; py[2] = pB.y; px[3] = pB.z; py[3] = pB.w;
    float qx[4] = {qA.x, qA.z, qB.x, qB.z};
    float qy[4] = {qA.y, qA.w, qB.y, qB.w};
    int cnt = 4;
#pragma unroll
    for (int kk = 0; kk < 4; kk++) {
        float p1x = qx[kk], p1y = qy[kk];
        int k2 = (kk + 1) & 3;
        float ex = qx[k2] - p1x, ey = qy[k2] - p1y;
        int oc = 0;
        float d0 = ex * (py[0] - p1y) - ey * (px[0] - p1x);
        float dc = d0;
        for (int i = 0; i < cnt; i++) {
            int nx = (i + 1 < cnt) ? i + 1 : 0;
            float dn = (i + 1 < cnt) ? (ex * (py[i + 1] - p1y) - ey * (px[i + 1] - p1x)) : d0;
            bool ci = dc >= 0.f, ni = dn >= 0.f;
            if (ci) { ox[oc] = px[i]; oy[oc] = py[i]; oc++; }
            if (ci != ni) {
                float den = dc - dn;
                float tt = dc / ((den == 0.f) ? 1.f : den);
                ox[oc] = px[i] + tt * (px[nx] - px[i]);
                oy[oc] = py[i] + tt * (py[nx] - py[i]);
                oc++;
            }
            dc = dn;
        }
        cnt = oc;
        if (cnt == 0) break;
        for (int i = 0; i < cnt; i++) { px[i] = ox[i]; py[i] = oy[i]; }
    }
    if (cnt < 3) return 0.f;
    float s = 0.f;
    for (int i = 0; i < cnt; i++) {
        int nx = (i + 1 < cnt) ? i + 1 : 0;
        s += px[i] * py[nx] - px[nx] * py[i];
    }
    return 0.5f * fabsf(s);
}

__global__ __launch_bounds__(256) void mask_kernel() {
    int grp = threadIdx.x >> 6, lane = threadIdx.x & 63;
    int tile = blockIdx.x * 4 + grp;            // 2112 tiles total
    int img = tile / 528, tri = tile % 528;
    int rb = 0, rowrem = 32;
    while (tri >= rowrem) { tri -= rowrem; rowrem--; rb++; }
    int cb = rb + tri;

    __shared__ float4 sg[4][64][4];
    const float4* gg = (const float4*)&g_geom[img][0][0];
    for (int i = lane; i < 256; i += 64)
        ((float4*)sg[grp])[i] = gg[cb * 256 + i];
    __syncthreads();

    int row = rb * 64 + lane;
    float4 rA = gg[row * 4 + 0];
    float4 rB = gg[row * 4 + 1];
    float4 rC = gg[row * 4 + 2];   // area, cx, cy, r
    float4 rD = gg[row * 4 + 3];   // xmin, xmax, ymin, ymax

    // pass 1: branchless cheap filters -> survivor bitmask
    unsigned long long surv = 0;
#pragma unroll 4
    for (int j = 0; j < 64; j++) {
        float4 cC = sg[grp][j][2];
        float ddx = rC.y - cC.y, ddy = rC.z - cC.z;
        float rr = rC.w + cC.w;
        float mn = fminf(rC.x, cC.x), mx = fmaxf(rC.x, cC.x);
        bool ok = (ddx * ddx + ddy * ddy < rr * rr) && (mn > 0.7f * mx);
        surv |= ((unsigned long long)ok) << j;
    }
    if (cb == rb) surv &= (lane < 63) ? (~0ull << (lane + 1)) : 0ull;

    // pass 2: exact checks only on survivors
    unsigned long long bits = 0;
    while (surv) {
        int j = __ffsll((long long)surv) - 1;
        surv &= surv - 1;
        float4 cC = sg[grp][j][2];
        float4 cD = sg[grp][j][3];
        float S = rC.x + cC.x;
        float xl = fmaxf(rD.x, cD.x), xr = fminf(rD.y, cD.y);
        float yl = fmaxf(rD.z, cD.z), yr = fminf(rD.w, cD.w);
        float ub = fmaxf(xr - xl, 0.f) * fmaxf(yr - yl, 0.f);
        if (ub * 1.7f < S * 0.6993f) continue;              // AABB bound (margin)
        float inter = inter_area(rA, rB, sg[grp][j][0], sg[grp][j][1]);
        float iou = inter / (S - inter + 1e-7f);
        if (iou > 0.7f) bits |= (1ull << j);
    }
    g_mask[img][row][cb] = bits;
    if (bits)
        atomicOr(&g_rowany[img][row >> 6], 1ull << (row & 63));
}

// ---------- stage 5 (fused): greedy scan + padded output write ------------
__global__ __launch_bounds__(512) void greedy_out_kernel(float* __restrict__ out) {
    int b = blockIdx.x;
    int tid = threadIdx.x;
    __shared__ int keep[PRE];
    __shared__ int s_n;
    if (tid < 32) {
        int lane = tid;
        unsigned long long remv = 0;
        const unsigned long long* vp = (const unsigned long long*)&g_svalid[b][lane * 64];
#pragma unroll
        for (int q = 0; q < 8; q++) {
            unsigned long long w8 = vp[q];
#pragma unroll
            for (int kk = 0; kk < 8; kk++)
                if (((w8 >> (kk * 8)) & 0xffull) == 0ull)
                    remv |= (1ull << (q * 8 + kk));
        }
        unsigned long long ra = g_rowany[b][lane];   // lane's 64-row "has bits" word
        int n = 0;
        for (int i = 0; i < NC; i++) {
            unsigned long long w = __shfl_sync(0xffffffffu, remv, (i >> 6));
            if (!((w >> (i & 63)) & 1ull)) {
                if (lane == 0) keep[n] = i;
                n++;
                unsigned long long raw = __shfl_sync(0xffffffffu, ra, (i >> 6));
                if ((raw >> (i & 63)) & 1ull)
                    remv |= g_mask[b][i][lane];      // rare: only rows with bits
                if (n >= PRE) break;
            }
        }
        if (lane == 0) s_n = n;
    }
    __syncthreads();
    int n = s_n;
    float v0 = 0, v1 = 0, v2 = 0, v3 = 0, v4 = 0, sc = 0;
    if (tid < n) {
        int i = keep[tid];
        v0 = g_sbox[b][i][0]; v1 = g_sbox[b][i][1];
        v2 = g_sbox[b][i][2]; v3 = g_sbox[b][i][3];
        v4 = g_sbox[b][i][4];
        sc = g_sscore[b][i];
    }
    float* ob = out + ((long long)b * PRE + tid) * 5;
    ob[0] = v0; ob[1] = v1; ob[2] = v2; ob[3] = v3; ob[4] = v4;
    out[NB * PRE * 5 + b * PRE + tid] = sc;
}

extern "C" void kernel_launch(void* const* d_in, const int* in_sizes, int n_in,
                              void* d_out, int out_size) {
    const float* obj[4] = {0, 0, 0, 0};
    const float* dlt[4] = {0, 0, 0, 0};
    const float* anch = 0;
    const int osz[4] = {786432, 196608, 49152, 12288};
    const int dsz[4] = {4718592, 1179648, 294912, 73728};
    for (int i = 0; i < n_in; i++) {
        int s = in_sizes[i];
        const float* p = (const float*)d_in[i];
        if (s == 5222400) { anch = p; continue; }
        for (int l = 0; l < 4; l++) {
            if (s == osz[l]) obj[l] = p;
            else if (s == dsz[l]) dlt[l] = p;
        }
    }
    init_kernel<<<1, 128>>>();
    select_kernel<<<NBLK, 256>>>(obj[0], obj[1], obj[2], obj[3]);
    sortdecode_kernel<<<16, 512>>>(dlt[0], dlt[1], dlt[2], dlt[3], anch);
    geom_kernel<<<NB, 512>>>();
    mask_kernel<<<528, 256>>>();
    greedy_out_kernel<<<NB, 512>>>((float*)d_out);
}

// round 7
// speedup vs baseline: 1.8170x; 1.0774x over previous
#include <cuda_runtime.h>

#define NB 4
#define PRE 512
#define NC 2048
#define TANCH 261120
#define NBIN 8192
#define CANDCAP 2048
#define NBLK 264

// ---------------- scratch (device globals; zero-initialized) --------------
__device__ int g_hist[16][NBIN];
__device__ int g_ccnt[16];
__device__ int g_segarr[16];                      // per-segment barrier counters
__device__ unsigned long long g_rowany[NB][32];   // per-row "has suppression bits"
__device__ unsigned long long g_cand[16][CANDCAP];
__device__ float g_box[NB][NC][5];                // pos-indexed
__device__ float g_score[NB][NC];                 // pos-indexed
__device__ unsigned char g_valid[NB][NC];         // pos-indexed
__device__ float g_geom[NB][NC][16];              // pos-indexed: corners, area, c, r, AABB
__device__ unsigned long long g_key[NB][NC];
__device__ int g_perm[NB][NC];                    // sorted rank -> pos
__device__ unsigned char g_svalid[NB][NC];        // sorted order
__device__ float g_sscore[NB][NC];                // sorted order
__device__ unsigned long long g_mask[NB][NC][32];

__device__ const int c_aoff[4] = {0, 196608, 245760, 258048};
__device__ const int c_segblk[4] = {48, 12, 4, 2};   // producer blocks per level

__device__ __forceinline__ unsigned fflip(float f) {
    unsigned u = __float_as_uint(f);
    return (u & 0x80000000u) ? ~u : (u | 0x80000000u);
}
__device__ __forceinline__ float funflip(unsigned u) {
    return __uint_as_float((u & 0x80000000u) ? (u ^ 0x80000000u) : ~u);
}

// block mapping: 66 blocks per image
// lvl0: 48 x 4096, lvl1: 12 x 4096, lvl2: 4 x 3072, lvl3: 2 x 1536
__device__ __forceinline__ void map_block(int bx, int& b, int& lvl, int& c0, int& n) {
    b = bx / 66;
    int t = bx % 66;
    if (t < 48)      { lvl = 0; c0 = t * 4096;        n = 4096; }
    else if (t < 60) { lvl = 1; c0 = (t - 48) * 4096; n = 4096; }
    else if (t < 64) { lvl = 2; c0 = (t - 60) * 3072; n = 3072; }
    else             { lvl = 3; c0 = (t - 64) * 1536; n = 1536; }
}

__device__ __forceinline__ void hist_add(int* h, unsigned bin) {
    unsigned m = __match_any_sync(0xffffffffu, bin);
    int leader = __ffs(m) - 1;
    if ((threadIdx.x & 31) == leader) atomicAdd(&h[bin], __popc(m));
}

// ---------------- stage 0: tiny init (per-replay resets) ------------------
__global__ void init_kernel() {
    int t = threadIdx.x;
    if (t < 16) g_segarr[t] = 0;
    if (t < 128) ((unsigned long long*)g_rowany)[t] = 0ull;
}

// ------------- stage 1 (fused): hist -> seg barrier -> thresh -> collect ---
__global__ __launch_bounds__(256) void select_kernel(const float* __restrict__ o0,
                                                     const float* __restrict__ o1,
                                                     const float* __restrict__ o2,
                                                     const float* __restrict__ o3) {
    __shared__ int h[NBIN];
    for (int i = threadIdx.x; i < NBIN; i += 256) h[i] = 0;
    __syncthreads();
    int b, lvl, c0, n;
    map_block(blockIdx.x, b, lvl, c0, n);
    const float* base = lvl == 0 ? o0 : lvl == 1 ? o1 : lvl == 2 ? o2 : o3;
    int H = 256 >> lvl, HW = H * H;
    int NL = 3 * HW;
    int seg = b * 4 + lvl;
    const float4* p4 = (const float4*)(base + (long long)b * NL + c0);
    int n4 = n >> 2;

    for (int m = threadIdx.x; m < n4; m += 256) {
        float4 v = p4[m];
        hist_add(h, fflip(v.x) >> 19);
        hist_add(h, fflip(v.y) >> 19);
        hist_add(h, fflip(v.z) >> 19);
        hist_add(h, fflip(v.w) >> 19);
    }
    __syncthreads();
    for (int i = threadIdx.x; i < NBIN; i += 256)
        if (h[i]) atomicAdd(&g_hist[seg][i], h[i]);

    // per-segment barrier: wait only for this segment's producer blocks
    __syncthreads();
    if (threadIdx.x == 0) {
        __threadfence();
        atomicAdd(&g_segarr[seg], 1);
        int need = c_segblk[lvl];
        while (atomicAdd(&g_segarr[seg], 0) < need) {}
        __threadfence();
    }
    __syncthreads();

    // threshold: 32 bins/thread cached in registers
    __shared__ int part[256];
    __shared__ int s_c, s_cum;
    __shared__ unsigned s_th;
    int loc[32];
    {
        int t = threadIdx.x;
        int s = 0;
#pragma unroll
        for (int k = 0; k < 32; k++) {
            loc[k] = __ldcg(&g_hist[seg][NBIN - 1 - t * 32 - k]);
            s += loc[k];
        }
        part[t] = s;
    }
    __syncthreads();
    if (threadIdx.x == 0) {
        int cum = 0, c = 255;
        for (int q = 0; q < 256; q++) {
            if (cum + part[q] >= PRE) { c = q; break; }
            cum += part[q];
        }
        s_c = c; s_cum = cum;
    }
    __syncthreads();
    if (threadIdx.x == s_c) {
        int c2 = s_cum, th = 0;
#pragma unroll
        for (int k = 0; k < 32; k++) {
            int bin = NBIN - 1 - threadIdx.x * 32 - k;
            c2 += loc[k];
            if (c2 >= PRE) { th = bin; break; }
        }
        s_th = (unsigned)th;
    }
    __syncthreads();
    unsigned th = s_th;

    for (int m = threadIdx.x; m < n4; m += 256) {
        float4 v = p4[m];
        float vals[4] = {v.x, v.y, v.z, v.w};
#pragma unroll
        for (int s = 0; s < 4; s++) {
            unsigned u = fflip(vals[s]);
            if ((u >> 19) >= th) {
                int gm = c0 + m * 4 + s;
                int idx = (gm % HW) * 3 + gm / HW;   // (y*W+x)*A + a order
                int pos = atomicAdd(&g_ccnt[seg], 1);
                if (pos < CANDCAP)
                    g_cand[seg][pos] = (((unsigned long long)u) << 32) | (unsigned)(~idx);
            }
        }
    }
}

// ------- stage 2: per-segment sort -> exact top-512 -> decode + geometry ---
__global__ __launch_bounds__(512) void sortdecode_kernel(const float* __restrict__ d0,
                                                         const float* __restrict__ d1,
                                                         const float* __restrict__ d2,
                                                         const float* __restrict__ d3,
                                                         const float* __restrict__ anchors) {
    int seg = blockIdx.x;
    int sb = seg >> 2, slvl = seg & 3;
    __shared__ unsigned long long sk[CANDCAP];
    __shared__ int wtot[16], woff[16];
    __shared__ int s_tot;
    int tid = threadIdx.x;
    int cnt = g_ccnt[seg];
    if (cnt > CANDCAP) cnt = CANDCAP;
    int M = (cnt <= 1024) ? 1024 : CANDCAP;
    for (int i = tid; i < M; i += 512)
        sk[i] = (i < cnt) ? g_cand[seg][i] : 0ull;
    __syncthreads();
    // re-zero scratch for next replay
    if (tid == 0) g_ccnt[seg] = 0;
    for (int i = tid; i < NBIN; i += 512) g_hist[seg][i] = 0;
    for (int ksz = 2; ksz <= M; ksz <<= 1) {
        for (int j = ksz >> 1; j > 0; j >>= 1) {
            for (int i = tid; i < M; i += 512) {
                int l = i ^ j;
                if (l > i) {
                    unsigned long long a = sk[i], c = sk[l];
                    bool desc = ((i & ksz) == 0);
                    if (desc ? (a < c) : (a > c)) { sk[i] = c; sk[l] = a; }
                }
            }
            __syncthreads();
        }
    }
    // decode (each of the 512 threads takes one entry)
    unsigned long long kk = sk[tid];
    float val = funflip((unsigned)(kk >> 32));
    int li = (int)(~(unsigned)(kk & 0xFFFFFFFFull));
    int sH = 256 >> slvl, sHW = sH * sH;
    int a = li % 3, cell = li / 3;
    int x = cell % sH, y = cell / sH;
    const float* dl = slvl == 0 ? d0 : slvl == 1 ? d1 : slvl == 2 ? d2 : d3;
    long long bi = ((long long)sb * 18 + a * 6) * sHW + (long long)y * sH + x;
    float dx = dl[bi], dy = dl[bi + sHW], dw = dl[bi + 2LL * sHW],
          dh = dl[bi + 3LL * sHW], ds = dl[bi + 4LL * sHW], dc = dl[bi + 5LL * sHW];
    int ta = c_aoff[slvl] + li;
    const float* an = anchors + ((long long)sb * TANCH + ta) * 5;
    float ax = an[0], ay = an[1], aw = an[2], ah = an[3], aa = an[4];
    const float LOGM = 4.135166556742356f;
    dw = fminf(dw, LOGM);
    dh = fminf(dh, LOGM);
    float bw = aw * expf(dw), bh = ah * expf(dh);
    float bcx = ax + dx * aw, bcy = ay + dy * ah;
    float ang = aa + atan2f(ds, dc);
    float sc = 0.5f + 0.5f * tanhf(0.5f * val);       // XLA logistic form
    bool vd = (bw >= 1e-3f) && (bh >= 1e-3f) && (sc >= 0.0f);

    // stable compaction: valids to front, invalids to tail, order preserved
    unsigned bal = __ballot_sync(0xffffffffu, vd);
    int lane = tid & 31, w = tid >> 5;
    int prew = __popc(bal & ((1u << lane) - 1u));
    if (lane == 0) wtot[w] = __popc(bal);
    __syncthreads();
    if (tid == 0) {
        int s = 0;
        for (int q = 0; q < 16; q++) { woff[q] = s; s += wtot[q]; }
        s_tot = s;
    }
    __syncthreads();
    int vbefore = woff[w] + prew;
    int rank = vd ? vbefore : (s_tot + (tid - vbefore));
    int pos = slvl * PRE + rank;

    g_box[sb][pos][0] = bcx; g_box[sb][pos][1] = bcy;
    g_box[sb][pos][2] = bw;  g_box[sb][pos][3] = bh;
    g_box[sb][pos][4] = ang;
    g_score[sb][pos] = sc;
    g_valid[sb][pos] = vd ? 1 : 0;
    unsigned u = vd ? __float_as_uint(sc) : 0u;       // score desc, pos asc tiebreak
    g_key[sb][pos] = (((unsigned long long)u) << 32) | (unsigned)(2047 - pos);

    // geometry (pos-indexed), values already in registers
    {
        float off = 8192.0f * (float)slvl;
        float cx = bcx + off, cy = bcy + off;
        float ca = cosf(ang), sa = sinf(ang);
        float hw = 0.5f * bw, hh = 0.5f * bh;
        float dxs[4] = {hw, -hw, -hw, hw};
        float dys[4] = {hh, hh, -hh, -hh};
        float xmn = 1e30f, xmx = -1e30f, ymn = 1e30f, ymx = -1e30f;
        float* gp = &g_geom[sb][pos][0];
#pragma unroll
        for (int c = 0; c < 4; c++) {
            float xx = cx + dxs[c] * ca - dys[c] * sa;
            float yy = cy + dxs[c] * sa + dys[c] * ca;
            gp[2 * c] = xx;
            gp[2 * c + 1] = yy;
            xmn = fminf(xmn, xx); xmx = fmaxf(xmx, xx);
            ymn = fminf(ymn, yy); ymx = fmaxf(ymx, yy);
        }
        gp[8] = bw * bh;
        gp[9] = cx;
        gp[10] = cy;
        gp[11] = 0.5f * sqrtf(bw * bw + bh * bh);
        gp[12] = xmn;
        gp[13] = xmx;
        gp[14] = ymn;
        gp[15] = ymx;
    }
}

// -------- stage 3: 4-way merge -> permutation (tiny) -----------------------
__device__ __forceinline__ unsigned long long merge_pick(
    const unsigned long long* A, const unsigned long long* B, int len, int i) {
    int lo = i > len ? i - len : 0;
    int hi = i < len ? i : len;
    while (lo < hi) {
        int a = (lo + hi) >> 1;
        if (A[a] > B[i - a - 1]) lo = a + 1; else hi = a;
    }
    int aa = lo, bb = i - lo;
    return (aa < len && (bb >= len || A[aa] > B[bb])) ? A[aa] : B[bb];
}

__global__ __launch_bounds__(512) void merge_kernel() {
    int b = blockIdx.x;
    __shared__ unsigned long long sk[NC];
    __shared__ unsigned long long tmp[NC];
    int tid = threadIdx.x;
    for (int i = tid; i < NC; i += 512) sk[i] = g_key[b][i];
    __syncthreads();
#pragma unroll
    for (int half = 0; half < 2; half++) {
        const unsigned long long* A = sk + half * 1024;
        for (int i = tid; i < 1024; i += 512)
            tmp[half * 1024 + i] = merge_pick(A, A + 512, 512, i);
    }
    __syncthreads();
    for (int i = tid; i < 2048; i += 512) {
        unsigned long long kk = merge_pick(tmp, tmp + 1024, 1024, i);
        int pos = 2047 - (int)(unsigned)(kk & 0xFFFFFFFFull);
        g_perm[b][i] = pos;
        unsigned char vd = g_valid[b][pos];
        g_svalid[b][i] = vd;
        g_sscore[b][i] = vd ? g_score[b][pos] : __int_as_float(0xff800000);
    }
}

// ---------------- stage 4: rotated IoU suppression bitmask -----------------
__device__ float inter_area(float4 pA, float4 pB, float4 qA, float4 qB) {
    float px[8], py[8], ox[8], oy[8];
    px[0] = pA.x; py[0] = pA.y; px[1] = pA.z; py[1] = pA.w;
    px[2] = pB.x; py[2] = pB.y; px[3] = pB.z; py[3] = pB.w;
    float qx[4] = {qA.x, qA.z, qB.x, qB.z};
    float qy[4] = {qA.y, qA.w, qB.y, qB.w};
    int cnt = 4;
#pragma unroll
    for (int kk = 0; kk < 4; kk++) {
        float p1x = qx[kk], p1y = qy[kk];
        int k2 = (kk + 1) & 3;
        float ex = qx[k2] - p1x, ey = qy[k2] - p1y;
        int oc = 0;
        float d0 = ex * (py[0] - p1y) - ey * (px[0] - p1x);
        float dc = d0;
        for (int i = 0; i < cnt; i++) {
            int nx = (i + 1 < cnt) ? i + 1 : 0;
            float dn = (i + 1 < cnt) ? (ex * (py[i + 1] - p1y) - ey * (px[i + 1] - p1x)) : d0;
            bool ci = dc >= 0.f, ni = dn >= 0.f;
            if (ci) { ox[oc] = px[i]; oy[oc] = py[i]; oc++; }
            if (ci != ni) {
                float den = dc - dn;
                float tt = dc / ((den == 0.f) ? 1.f : den);
                ox[oc] = px[i] + tt * (px[nx] - px[i]);
                oy[oc] = py[i] + tt * (py[nx] - py[i]);
                oc++;
            }
            dc = dn;
        }
        cnt = oc;
        if (cnt == 0) break;
        for (int i = 0; i < cnt; i++) { px[i] = ox[i]; py[i] = oy[i]; }
    }
    if (cnt < 3) return 0.f;
    float s = 0.f;
    for (int i = 0; i < cnt; i++) {
        int nx = (i + 1 < cnt) ? i + 1 : 0;
        s += px[i] * py[nx] - px[nx] * py[i];
    }
    return 0.5f * fabsf(s);
}

__global__ __launch_bounds__(256) void mask_kernel() {
    int grp = threadIdx.x >> 6, lane = threadIdx.x & 63;
    int tile = blockIdx.x * 4 + grp;            // 2112 tiles total
    int img = tile / 528, tri = tile % 528;
    int rb = 0, rowrem = 32;
    while (tri >= rowrem) { tri -= rowrem; rowrem--; rb++; }
    int cb = rb + tri;

    __shared__ float4 sg[4][64][4];
    __shared__ int sperm[4][64];
    const float4* gg = (const float4*)&g_geom[img][0][0];
    sperm[grp][lane] = g_perm[img][cb * 64 + lane];
    int prow = g_perm[img][rb * 64 + lane];
    __syncthreads();
    for (int i = lane; i < 256; i += 64) {
        int box = i >> 2, k = i & 3;
        sg[grp][box][k] = gg[sperm[grp][box] * 4 + k];
    }
    __syncthreads();

    int row = rb * 64 + lane;
    float4 rA = gg[prow * 4 + 0];
    float4 rB = gg[prow * 4 + 1];
    float4 rC = gg[prow * 4 + 2];   // area, cx, cy, r
    float4 rD = gg[prow * 4 + 3];   // xmin, xmax, ymin, ymax

    // pass 1: branchless cheap filters -> survivor bitmask
    unsigned long long surv = 0;
#pragma unroll 4
    for (int j = 0; j < 64; j++) {
        float4 cC = sg[grp][j][2];
        float ddx = rC.y - cC.y, ddy = rC.z - cC.z;
        float rr = rC.w + cC.w;
        float mn = fminf(rC.x, cC.x), mx = fmaxf(rC.x, cC.x);
        bool ok = (ddx * ddx + ddy * ddy < rr * rr) && (mn > 0.7f * mx);
        surv |= ((unsigned long long)ok) << j;
    }
    if (cb == rb) surv &= (lane < 63) ? (~0ull << (lane + 1)) : 0ull;

    // pass 2: exact checks only on survivors
    unsigned long long bits = 0;
    while (surv) {
        int j = __ffsll((long long)surv) - 1;
        surv &= surv - 1;
        float4 cC = sg[grp][j][2];
        float4 cD = sg[grp][j][3];
        float S = rC.x + cC.x;
        float xl = fmaxf(rD.x, cD.x), xr = fminf(rD.y, cD.y);
        float yl = fmaxf(rD.z, cD.z), yr = fminf(rD.w, cD.w);
        float ub = fmaxf(xr - xl, 0.f) * fmaxf(yr - yl, 0.f);
        if (ub * 1.7f < S * 0.6993f) continue;              // AABB bound (margin)
        float inter = inter_area(rA, rB, sg[grp][j][0], sg[grp][j][1]);
        float iou = inter / (S - inter + 1e-7f);
        if (iou > 0.7f) bits |= (1ull << j);
    }
    g_mask[img][row][cb] = bits;
    if (bits)
        atomicOr(&g_rowany[img][row >> 6], 1ull << (row & 63));
}

// ---------- stage 5 (fused): greedy scan + padded output write ------------
__global__ __launch_bounds__(512) void greedy_out_kernel(float* __restrict__ out) {
    int b = blockIdx.x;
    int tid = threadIdx.x;
    __shared__ int keep[PRE];
    __shared__ int s_n;
    if (tid < 32) {
        int lane = tid;
        unsigned long long remv = 0;
        const unsigned long long* vp = (const unsigned long long*)&g_svalid[b][lane * 64];
#pragma unroll
        for (int q = 0; q < 8; q++) {
            unsigned long long w8 = vp[q];
#pragma unroll
            for (int kk = 0; kk < 8; kk++)
                if (((w8 >> (kk * 8)) & 0xffull) == 0ull)
                    remv |= (1ull << (q * 8 + kk));
        }
        unsigned long long ra = g_rowany[b][lane];   // lane's 64-row "has bits" word
        int n = 0;
        for (int i = 0; i < NC; i++) {
            unsigned long long w = __shfl_sync(0xffffffffu, remv, (i >> 6));
            if (!((w >> (i & 63)) & 1ull)) {
                if (lane == 0) keep[n] = i;
                n++;
                unsigned long long raw = __shfl_sync(0xffffffffu, ra, (i >> 6));
                if ((raw >> (i & 63)) & 1ull)
                    remv |= g_mask[b][i][lane];      // rare: only rows with bits
                if (n >= PRE) break;
            }
        }
        if (lane == 0) s_n = n;
    }
    __syncthreads();
    int n = s_n;
    float v0 = 0, v1 = 0, v2 = 0, v3 = 0, v4 = 0, sc = 0;
    if (tid < n) {
        int i = keep[tid];
        int pos = g_perm[b][i];
        v0 = g_box[b][pos][0]; v1 = g_box[b][pos][1];
        v2 = g_box[b][pos][2]; v3 = g_box[b][pos][3];
        v4 = g_box[b][pos][4];
        sc = g_sscore[b][i];
    }
    float* ob = out + ((long long)b * PRE + tid) * 5;
    ob[0] = v0; ob[1] = v1; ob[2] = v2; ob[3] = v3; ob[4] = v4;
    out[NB * PRE * 5 + b * PRE + tid] = sc;
}

extern "C" void kernel_launch(void* const* d_in, const int* in_sizes, int n_in,
                              void* d_out, int out_size) {
    const float* obj[4] = {0, 0, 0, 0};
    const float* dlt[4] = {0, 0, 0, 0};
    const float* anch = 0;
    const int osz[4] = {786432, 196608, 49152, 12288};
    const int dsz[4] = {4718592, 1179648, 294912, 73728};
    for (int i = 0; i < n_in; i++) {
        int s = in_sizes[i];
        const float* p = (const float*)d_in[i];
        if (s == 5222400) { anch = p; continue; }
        for (int l = 0; l < 4; l++) {
            if (s == osz[l]) obj[l] = p;
            else if (s == dsz[l]) dlt[l] = p;
        }
    }
    init_kernel<<<1, 128>>>();
    select_kernel<<<NBLK, 256>>>(obj[0], obj[1], obj[2], obj[3]);
    sortdecode_kernel<<<16, 512>>>(dlt[0], dlt[1], dlt[2], dlt[3], anch);
    merge_kernel<<<NB, 512>>>();
    mask_kernel<<<528, 256>>>();
    greedy_out_kernel<<<NB, 512>>>((float*)d_out);
}